// round 3
// baseline (speedup 1.0000x reference)
#include <cuda_runtime.h>
#include <cstdint>
#include <cstddef>

#define T_DATA 100000
#define NG     24
#define TNO    200
#define ESYN   2000
#define ISYN   500
#define NCB    13
#define NOB    29
#define OLEN   401
#define PAD    256
#define SUFF   1536
#define TPAD   (PAD + T_DATA + SUFF)
#define TILE   1024
#define NELEM  (T_DATA * NG)
#define OBS_TT 256
#define NSPK_MAX 16384

// ---------------- device scratch (static, zero-initialized) ----------------
__device__ float2 g_syn2[NG][TPAD];  // (E,I) drive pairs per subunit, zero pads
__device__ float  g_ke[NG][TNO];     // e kernel (unflipped, Kc)
__device__ float  g_ki[NG][TNO];     // i kernel (negated, unflipped)
__device__ float  g_K[NG][OLEN];     // obs kernel K[g][d], d = 200 + t - s
__device__ int    g_idxE[ESYN];
__device__ int    g_idxI[ISYN];
__device__ int    g_spk[NSPK_MAX];   // sorted Z spike times
__device__ int    g_nspk;
__device__ float  g_obs[NELEM];      // obs_filt[t][g]
__device__ float  g_scratchP[NELEM]; // fallback P storage

// ---------------- setup: kernels + connectivity index ----------------------
__global__ void setup_kernel(const float* __restrict__ Ce,
                             const float* __restrict__ Ci,
                             const float* __restrict__ Wsyn,
                             const float* __restrict__ Wobs,
                             const float* __restrict__ cosb,
                             const float* __restrict__ obsb) {
    int k = blockIdx.x * blockDim.x + threadIdx.x;
    if (k < ESYN) {
        int gf = -1;
        for (int r = 1; r <= NG; ++r)
            if (Ce[r * ESYN + k] != 0.0f) gf = r - 1;
        g_idxE[k] = gf;
        return;
    }
    k -= ESYN;
    if (k < ISYN) {
        int gf = -1;
        for (int r = 1; r <= NG; ++r)
            if (Ci[r * ISYN + k] != 0.0f) gf = r - 1;
        g_idxI[k] = gf;
        return;
    }
    k -= ISYN;
    if (k < NG * TNO) {  // e kernel
        int g = k / TNO, j = k % TNO;
        float s = 0.0f;
        for (int b = 0; b < NCB; ++b) {
            float w = Wsyn[(g * NCB + b) * 2 + 0];
            s += (w * w) * cosb[b * TNO + j];
        }
        g_ke[g][j] = s;
        return;
    }
    k -= NG * TNO;
    if (k < NG * TNO) {  // i kernel (negated)
        int g = k / TNO, j = k % TNO;
        float s = 0.0f;
        for (int b = 0; b < NCB; ++b) {
            float w = Wsyn[(g * NCB + b) * 2 + 1];
            s += (w * w) * cosb[b * TNO + j];
        }
        g_ki[g][j] = -s;
        return;
    }
    k -= NG * TNO;
    if (k < NG * OLEN) {  // obs kernel K = W_obs @ obs_basis (unflipped)
        int g = k / OLEN, j = k % OLEN;
        float s = 0.0f;
        for (int b = 0; b < NOB; ++b)
            s += Wobs[g * NOB + b] * obsb[b * OLEN + j];
        g_K[g][j] = s;
    }
}

// ---------------- sorted spike list of Z (single block scan) ---------------
__global__ void spk_kernel(const float* __restrict__ Z) {
    __shared__ int wsum[33];
    int tid = threadIdx.x;                    // 1024 threads
    int lane = tid & 31, wid = tid >> 5;
    const int CH = (T_DATA + 1023) / 1024;    // 98
    int a = tid * CH;
    int b = a + CH; if (b > T_DATA) b = T_DATA;
    int c = 0;
    for (int t = a; t < b; ++t) c += (Z[t] != 0.0f);
    int v = c;
    for (int o = 1; o < 32; o <<= 1) {
        int n = __shfl_up_sync(0xffffffffu, v, o);
        if (lane >= o) v += n;
    }
    if (lane == 31) wsum[wid] = v;
    __syncthreads();
    if (wid == 0) {
        int s = wsum[lane];
        __syncwarp();
        for (int o = 1; o < 32; o <<= 1) {
            int n = __shfl_up_sync(0xffffffffu, s, o);
            if (lane >= o) s += n;
        }
        wsum[lane + 1] = s;
        if (lane == 0) wsum[0] = 0;
    }
    __syncthreads();
    int pos = wsum[wid] + (v - c);
    for (int t = a; t < b; ++t)
        if (Z[t] != 0.0f) g_spk[pos++] = t;
    if (tid == 1023) g_nspk = wsum[32];
}

// ---------------- spike binning: the HBM-bound kernel ----------------------
__global__ void __launch_bounds__(256) bin_kernel(const uint4* __restrict__ Se,
                                                  const uint4* __restrict__ Si) {
    __shared__ float sb[8][64];   // [row][0..23]=E bins, [32..55]=I bins
    int w = threadIdx.x >> 5, l = threadIdx.x & 31;
    int t = blockIdx.x * 8 + w;
    for (int i = threadIdx.x; i < 8 * 64; i += 256) ((float*)sb)[i] = 0.0f;
    __syncthreads();

    const uint4* rowE = Se + (size_t)t * (ESYN / 4);
    #pragma unroll 2
    for (int i = l; i < ESYN / 4; i += 32) {
        uint4 v = __ldcs(rowE + i);
        if (v.x | v.y | v.z | v.w) {
            if (v.x) { int g = g_idxE[4 * i + 0]; if (g >= 0) atomicAdd(&sb[w][g], __uint_as_float(v.x)); }
            if (v.y) { int g = g_idxE[4 * i + 1]; if (g >= 0) atomicAdd(&sb[w][g], __uint_as_float(v.y)); }
            if (v.z) { int g = g_idxE[4 * i + 2]; if (g >= 0) atomicAdd(&sb[w][g], __uint_as_float(v.z)); }
            if (v.w) { int g = g_idxE[4 * i + 3]; if (g >= 0) atomicAdd(&sb[w][g], __uint_as_float(v.w)); }
        }
    }
    const uint4* rowI = Si + (size_t)t * (ISYN / 4);
    #pragma unroll 2
    for (int i = l; i < ISYN / 4; i += 32) {
        uint4 v = __ldcs(rowI + i);
        if (v.x | v.y | v.z | v.w) {
            if (v.x) { int g = g_idxI[4 * i + 0]; if (g >= 0) atomicAdd(&sb[w][32 + g], __uint_as_float(v.x)); }
            if (v.y) { int g = g_idxI[4 * i + 1]; if (g >= 0) atomicAdd(&sb[w][32 + g], __uint_as_float(v.y)); }
            if (v.z) { int g = g_idxI[4 * i + 2]; if (g >= 0) atomicAdd(&sb[w][32 + g], __uint_as_float(v.z)); }
            if (v.w) { int g = g_idxI[4 * i + 3]; if (g >= 0) atomicAdd(&sb[w][32 + g], __uint_as_float(v.w)); }
        }
    }
    __syncthreads();
    // writeback (E,I) pairs; kk = g*8+row keeps stores coalesced in t
    for (int kk = threadIdx.x; kk < NG * 8; kk += 256) {
        int g = kk >> 3, row = kk & 7;
        int tt = blockIdx.x * 8 + row;
        g_syn2[g][PAD + tt] = make_float2(sb[row][g], sb[row][32 + g]);
    }
}

// ---------------- sparse obs (spike-history) filter -------------------------
__global__ void __launch_bounds__(256) obs_kernel() {
    __shared__ float sko[NG][404];
    __shared__ float sOut[OBS_TT * 25];
    __shared__ int   sspk[128];
    int tid = threadIdx.x;
    int t0 = blockIdx.x * OBS_TT;

    for (int i = tid; i < NG * OLEN; i += 256)
        sko[i / OLEN][i % OLEN] = ((const float*)g_K)[i];

    int n = g_nspk;
    int L = t0 - 200, R = t0 + OBS_TT - 1 + 200;
    int lo = 0, hi = n;
    while (lo < hi) { int m = (lo + hi) >> 1; if (g_spk[m] < L) lo = m + 1; else hi = m; }
    int beg = lo;
    hi = n;
    while (lo < hi) { int m = (lo + hi) >> 1; if (g_spk[m] <= R) lo = m + 1; else hi = m; }
    int end = lo;

    float acc[NG];
    #pragma unroll
    for (int g = 0; g < NG; ++g) acc[g] = 0.0f;
    int t = t0 + tid;
    __syncthreads();  // sko ready

    for (int base = beg; base < end; base += 128) {
        int m = end - base; if (m > 128) m = 128;
        if (tid < m) sspk[tid] = g_spk[base + tid];
        __syncthreads();
        for (int k = 0; k < m; ++k) {
            int d = t - sspk[k] + 200;
            if ((unsigned)d <= 400u) {
                #pragma unroll
                for (int g = 0; g < NG; ++g) acc[g] += sko[g][d];
            }
        }
        __syncthreads();
    }
    #pragma unroll
    for (int g = 0; g < NG; ++g) sOut[tid * 25 + g] = acc[g];
    __syncthreads();
    for (int i = tid; i < OBS_TT * NG; i += 256) {
        int tt = i / NG, g = i - tt * NG;
        int tg = t0 + tt;
        if (tg < T_DATA) g_obs[(size_t)tg * NG + g] = sOut[tt * 25 + g];
    }
}

// ---------------- threefry2x32 (jax partitionable path) ---------------------
__device__ __forceinline__ uint32_t rotl32(uint32_t x, int r) {
    return (x << r) | (x >> (32 - r));
}
__device__ __forceinline__ void threefry_0_42(uint32_t c0, uint32_t c1,
                                              uint32_t& o0, uint32_t& o1) {
    const uint32_t k0 = 0u, k1 = 42u, k2 = 0x1BD11BDAu ^ 0u ^ 42u;
    uint32_t x0 = c0 + k0, x1 = c1 + k1;
#define RND(r) { x0 += x1; x1 = rotl32(x1, (r)); x1 ^= x0; }
    RND(13) RND(15) RND(26) RND(6)   x0 += k1; x1 += k2 + 1u;
    RND(17) RND(29) RND(16) RND(24)  x0 += k2; x1 += k0 + 2u;
    RND(13) RND(15) RND(26) RND(6)   x0 += k0; x1 += k1 + 3u;
    RND(17) RND(29) RND(16) RND(24)  x0 += k1; x1 += k2 + 4u;
    RND(13) RND(15) RND(26) RND(6)   x0 += k2; x1 += k0 + 5u;
#undef RND
    o0 = x0; o1 = x1;
}

// ---------------- fused e/i convs + sigmoid + bernoulli --------------------
__global__ void __launch_bounds__(256) glm_kernel(const float* __restrict__ Theta,
                                                  float* __restrict__ Zo,
                                                  float* __restrict__ Po_opt) {
    __shared__ __align__(16) float sE[TILE + 200 + 8];
    __shared__ __align__(16) float sI[TILE + 200 + 8];
    __shared__ __align__(16) float ske[TNO];   // reversed
    __shared__ __align__(16) float ski[TNO];   // reversed

    float* Po = Po_opt ? Po_opt : (float*)g_scratchP;
    int g = blockIdx.x;
    int t0 = blockIdx.y * TILE;
    int base = PAD + t0 - 200;

    for (int i = threadIdx.x; i < TILE + 200; i += 256) {
        float2 v = g_syn2[g][base + i];
        sE[i] = v.x; sI[i] = v.y;
    }
    for (int i = threadIdx.x; i < TNO; i += 256) {
        ske[i] = g_ke[g][TNO - 1 - i];
        ski[i] = g_ki[g][TNO - 1 - i];
    }
    __syncthreads();

    const int tid = threadIdx.x;
    float a0 = 0.f, a1 = 0.f, a2 = 0.f, a3 = 0.f;

    {   // e conv
        const float4* d4 = (const float4*)sE;
        const float4* k4 = (const float4*)ske;
        float4 cur = d4[tid];
        #pragma unroll 2
        for (int q = 0; q < TNO / 4; ++q) {
            float4 kk = k4[q];
            float4 nxt = d4[tid + q + 1];
            a0 += kk.x * cur.x; a1 += kk.x * cur.y; a2 += kk.x * cur.z; a3 += kk.x * cur.w;
            a0 += kk.y * cur.y; a1 += kk.y * cur.z; a2 += kk.y * cur.w; a3 += kk.y * nxt.x;
            a0 += kk.z * cur.z; a1 += kk.z * cur.w; a2 += kk.z * nxt.x; a3 += kk.z * nxt.y;
            a0 += kk.w * cur.w; a1 += kk.w * nxt.x; a2 += kk.w * nxt.y; a3 += kk.w * nxt.z;
            cur = nxt;
        }
    }
    {   // i conv
        const float4* d4 = (const float4*)sI;
        const float4* k4 = (const float4*)ski;
        float4 cur = d4[tid];
        #pragma unroll 2
        for (int q = 0; q < TNO / 4; ++q) {
            float4 kk = k4[q];
            float4 nxt = d4[tid + q + 1];
            a0 += kk.x * cur.x; a1 += kk.x * cur.y; a2 += kk.x * cur.z; a3 += kk.x * cur.w;
            a0 += kk.y * cur.y; a1 += kk.y * cur.z; a2 += kk.y * cur.w; a3 += kk.y * nxt.x;
            a0 += kk.z * cur.z; a1 += kk.z * cur.w; a2 += kk.z * nxt.x; a3 += kk.z * nxt.y;
            a0 += kk.w * cur.w; a1 += kk.w * nxt.x; a2 += kk.w * nxt.y; a3 += kk.w * nxt.z;
            cur = nxt;
        }
    }

    float th = Theta[g];
    float acc[4] = {a0, a1, a2, a3};
    int t = t0 + tid * 4;
    #pragma unroll
    for (int r = 0; r < 4; ++r) {
        if (t + r < T_DATA) {
            int idx = (t + r) * NG + g;
            float xf = acc[r] + th + g_obs[idx];
            double p = 1.0 / (1.0 + exp(-(double)xf));
            float pf = (float)p;
            uint32_t y0, y1;
            threefry_0_42(0u, (uint32_t)idx, y0, y1);
            uint32_t bits = y0 ^ y1;
            float u = __uint_as_float((bits >> 9) | 0x3f800000u) - 1.0f;
            Zo[idx] = (u < pf) ? 1.0f : 0.0f;
            Po[idx] = pf;
        }
    }
}

// ---------------- launcher --------------------------------------------------
extern "C" void kernel_launch(void* const* d_in, const int* in_sizes, int n_in,
                              void* d_out, int out_size) {
    const float *Z = 0, *Se = 0, *Si = 0, *Ce = 0, *Ci = 0;
    const float *Wsyn = 0, *Th = 0, *Wobs = 0, *cb = 0, *ob = 0;
    for (int i = 0; i < n_in; ++i) {
        switch (in_sizes[i]) {
            case 100000:    Z    = (const float*)d_in[i]; break;
            case 200000000: Se   = (const float*)d_in[i]; break;
            case 50000000:  Si   = (const float*)d_in[i]; break;
            case 50000:     Ce   = (const float*)d_in[i]; break;
            case 12500:     Ci   = (const float*)d_in[i]; break;
            case 624:       Wsyn = (const float*)d_in[i]; break;
            case 24:        Th   = (const float*)d_in[i]; break;
            case 696:       Wobs = (const float*)d_in[i]; break;
            case 2600:      cb   = (const float*)d_in[i]; break;
            case 11629:     ob   = (const float*)d_in[i]; break;
            default: break;
        }
    }
    float* out = (float*)d_out;
    float* Pdst = (out_size >= 2 * NELEM) ? (out + NELEM) : nullptr;

    const int setup_work = ESYN + ISYN + 2 * NG * TNO + NG * OLEN;
    setup_kernel<<<(setup_work + 255) / 256, 256>>>(Ce, Ci, Wsyn, Wobs, cb, ob);
    spk_kernel<<<1, 1024>>>(Z);
    bin_kernel<<<T_DATA / 8, 256>>>((const uint4*)Se, (const uint4*)Si);
    obs_kernel<<<(T_DATA + OBS_TT - 1) / OBS_TT, 256>>>();
    dim3 gridG(NG, (T_DATA + TILE - 1) / TILE);
    glm_kernel<<<gridG, 256>>>(Th, out, Pdst);
}

// round 4
// speedup vs baseline: 1.4000x; 1.4000x over previous
#include <cuda_runtime.h>
#include <cstdint>
#include <cstddef>

#define T_DATA 100000
#define NG     24
#define TNO    200
#define ESYN   2000
#define ISYN   500
#define NCB    13
#define NOB    29
#define OLEN   401
#define PAD    256
#define SUFF   1536
#define TPAD   (PAD + T_DATA + SUFF)
#define TILE   1024
#define NELEM  (T_DATA * NG)
#define TXP    100352            /* padded T for [g][t] planes (16B-aligned rows) */
#define NCHUNK 391               /* ceil(T_DATA/256) spike buckets */
#define SPKCAP 96

// ---------------- device scratch (static, zero-initialized) ----------------
__device__ float2 g_syn2[NG][TPAD];   // (E,I) drive pairs per subunit, zero pads
__device__ float  g_ke[NG][TNO];      // e kernel (unflipped)
__device__ float  g_ki[NG][TNO];      // i kernel (negated, unflipped)
__device__ float  g_K[NG][OLEN];      // obs kernel K[g][d], d = 200 + t - s
__device__ int    g_idxE[ESYN];
__device__ int    g_idxI[ISYN];
__device__ int    g_scnt[NCHUNK];     // per-chunk spike counts (zeroed in setup)
__device__ int    g_sbuf[NCHUNK][SPKCAP];
__device__ float  g_obs[NG][TXP];     // obs_filt, [g][t] layout (tail stays 0)
__device__ float  g_x[NG][TXP];       // pre-activation x = conv + th + obs
__device__ float  g_scratchP[NELEM];  // fallback P storage

// ---------------- setup: kernels + connectivity index + count reset --------
__global__ void setup_kernel(const float* __restrict__ Ce,
                             const float* __restrict__ Ci,
                             const float* __restrict__ Wsyn,
                             const float* __restrict__ Wobs,
                             const float* __restrict__ cosb,
                             const float* __restrict__ obsb) {
    int k = blockIdx.x * blockDim.x + threadIdx.x;
    if (k < ESYN) {
        int gf = -1;
        for (int r = 1; r <= NG; ++r)
            if (Ce[r * ESYN + k] != 0.0f) gf = r - 1;
        g_idxE[k] = gf;
        return;
    }
    k -= ESYN;
    if (k < ISYN) {
        int gf = -1;
        for (int r = 1; r <= NG; ++r)
            if (Ci[r * ISYN + k] != 0.0f) gf = r - 1;
        g_idxI[k] = gf;
        return;
    }
    k -= ISYN;
    if (k < NG * TNO) {  // e kernel
        int g = k / TNO, j = k % TNO;
        float s = 0.0f;
        for (int b = 0; b < NCB; ++b) {
            float w = Wsyn[(g * NCB + b) * 2 + 0];
            s += (w * w) * cosb[b * TNO + j];
        }
        g_ke[g][j] = s;
        return;
    }
    k -= NG * TNO;
    if (k < NG * TNO) {  // i kernel (negated)
        int g = k / TNO, j = k % TNO;
        float s = 0.0f;
        for (int b = 0; b < NCB; ++b) {
            float w = Wsyn[(g * NCB + b) * 2 + 1];
            s += (w * w) * cosb[b * TNO + j];
        }
        g_ki[g][j] = -s;
        return;
    }
    k -= NG * TNO;
    if (k < NG * OLEN) {  // obs kernel K = W_obs @ obs_basis (unflipped)
        int g = k / OLEN, j = k % OLEN;
        float s = 0.0f;
        for (int b = 0; b < NOB; ++b)
            s += Wobs[g * NOB + b] * obsb[b * OLEN + j];
        g_K[g][j] = s;
        return;
    }
    k -= NG * OLEN;
    if (k < NCHUNK) g_scnt[k] = 0;
}

// ---------------- spike bucketing (unordered within 256-t chunks) -----------
__global__ void spkb_kernel(const float* __restrict__ Z) {
    int t = blockIdx.x * blockDim.x + threadIdx.x;
    if (t < T_DATA && Z[t] != 0.0f) {
        int c = t >> 8;
        int p = atomicAdd(&g_scnt[c], 1);
        if (p < SPKCAP) g_sbuf[c][p] = t;
    }
}

// ---------------- sparse obs (spike-history) filter -------------------------
__global__ void __launch_bounds__(256) obs_kernel() {
    __shared__ float sko[NG][404];
    int tid = threadIdx.x;
    int t0 = blockIdx.x * 256;

    for (int i = tid; i < NG * OLEN; i += 256)
        sko[i / OLEN][i % OLEN] = ((const float*)g_K)[i];
    __syncthreads();

    float acc[NG];
    #pragma unroll
    for (int g = 0; g < NG; ++g) acc[g] = 0.0f;
    int t = t0 + tid;

    int cc = t0 >> 8;
    int c0 = cc > 0 ? cc - 1 : 0;
    int c1 = cc + 1 < NCHUNK ? cc + 1 : NCHUNK - 1;
    for (int c = c0; c <= c1; ++c) {
        int n = g_scnt[c];
        if (n > SPKCAP) n = SPKCAP;
        for (int k = 0; k < n; ++k) {
            int s = g_sbuf[c][k];
            int d = t - s + 200;
            if ((unsigned)d <= 400u) {
                #pragma unroll
                for (int g = 0; g < NG; ++g) acc[g] += sko[g][d];
            }
        }
    }
    if (t < T_DATA) {
        #pragma unroll
        for (int g = 0; g < NG; ++g) g_obs[g][t] = acc[g];
    }
}

// ---------------- spike binning: the big streaming kernel -------------------
__global__ void __launch_bounds__(256) bin_kernel(const float4* __restrict__ Se,
                                                  const float4* __restrict__ Si) {
    __shared__ float sb[8][64];   // [row][0..23]=E bins, [32..55]=I bins
    int w = threadIdx.x >> 5, l = threadIdx.x & 31;
    int t = blockIdx.x * 8 + w;
    for (int i = threadIdx.x; i < 8 * 64; i += 256) ((float*)sb)[i] = 0.0f;
    __syncthreads();

    const float4* rowE = Se + (size_t)t * (ESYN / 4);
    for (int i = l; i < ESYN / 4; i += 32) {
        float4 v = rowE[i];
        if (v.x != 0.0f) { int g = g_idxE[4 * i + 0]; if (g >= 0) atomicAdd(&sb[w][g], v.x); }
        if (v.y != 0.0f) { int g = g_idxE[4 * i + 1]; if (g >= 0) atomicAdd(&sb[w][g], v.y); }
        if (v.z != 0.0f) { int g = g_idxE[4 * i + 2]; if (g >= 0) atomicAdd(&sb[w][g], v.z); }
        if (v.w != 0.0f) { int g = g_idxE[4 * i + 3]; if (g >= 0) atomicAdd(&sb[w][g], v.w); }
    }
    const float4* rowI = Si + (size_t)t * (ISYN / 4);
    for (int i = l; i < ISYN / 4; i += 32) {
        float4 v = rowI[i];
        if (v.x != 0.0f) { int g = g_idxI[4 * i + 0]; if (g >= 0) atomicAdd(&sb[w][32 + g], v.x); }
        if (v.y != 0.0f) { int g = g_idxI[4 * i + 1]; if (g >= 0) atomicAdd(&sb[w][32 + g], v.y); }
        if (v.z != 0.0f) { int g = g_idxI[4 * i + 2]; if (g >= 0) atomicAdd(&sb[w][32 + g], v.z); }
        if (v.w != 0.0f) { int g = g_idxI[4 * i + 3]; if (g >= 0) atomicAdd(&sb[w][32 + g], v.w); }
    }
    __syncthreads();
    for (int kk = threadIdx.x; kk < NG * 8; kk += 256) {
        int g = kk >> 3, row = kk & 7;
        int tt = blockIdx.x * 8 + row;
        g_syn2[g][PAD + tt] = make_float2(sb[row][g], sb[row][32 + g]);
    }
}

// ---------------- e/i convs -> pre-activation x[g][t] (all coalesced) -------
__global__ void __launch_bounds__(256) glm_kernel(const float* __restrict__ Theta) {
    __shared__ __align__(16) float sE[TILE + 200 + 8];
    __shared__ __align__(16) float sI[TILE + 200 + 8];
    __shared__ __align__(16) float ske[TNO];   // reversed
    __shared__ __align__(16) float ski[TNO];   // reversed

    int g = blockIdx.x;
    int t0 = blockIdx.y * TILE;
    int base = PAD + t0 - 200;

    for (int i = threadIdx.x; i < TILE + 200; i += 256) {
        float2 v = g_syn2[g][base + i];
        sE[i] = v.x; sI[i] = v.y;
    }
    for (int i = threadIdx.x; i < TNO; i += 256) {
        ske[i] = g_ke[g][TNO - 1 - i];
        ski[i] = g_ki[g][TNO - 1 - i];
    }
    __syncthreads();

    const int tid = threadIdx.x;
    float a0 = 0.f, a1 = 0.f, a2 = 0.f, a3 = 0.f;

    {   // e conv
        const float4* d4 = (const float4*)sE;
        const float4* k4 = (const float4*)ske;
        float4 cur = d4[tid];
        #pragma unroll 2
        for (int q = 0; q < TNO / 4; ++q) {
            float4 kk = k4[q];
            float4 nxt = d4[tid + q + 1];
            a0 += kk.x * cur.x; a1 += kk.x * cur.y; a2 += kk.x * cur.z; a3 += kk.x * cur.w;
            a0 += kk.y * cur.y; a1 += kk.y * cur.z; a2 += kk.y * cur.w; a3 += kk.y * nxt.x;
            a0 += kk.z * cur.z; a1 += kk.z * cur.w; a2 += kk.z * nxt.x; a3 += kk.z * nxt.y;
            a0 += kk.w * cur.w; a1 += kk.w * nxt.x; a2 += kk.w * nxt.y; a3 += kk.w * nxt.z;
            cur = nxt;
        }
    }
    {   // i conv
        const float4* d4 = (const float4*)sI;
        const float4* k4 = (const float4*)ski;
        float4 cur = d4[tid];
        #pragma unroll 2
        for (int q = 0; q < TNO / 4; ++q) {
            float4 kk = k4[q];
            float4 nxt = d4[tid + q + 1];
            a0 += kk.x * cur.x; a1 += kk.x * cur.y; a2 += kk.x * cur.z; a3 += kk.x * cur.w;
            a0 += kk.y * cur.y; a1 += kk.y * cur.z; a2 += kk.y * cur.w; a3 += kk.y * nxt.x;
            a0 += kk.z * cur.z; a1 += kk.z * cur.w; a2 += kk.z * nxt.x; a3 += kk.z * nxt.y;
            a0 += kk.w * cur.w; a1 += kk.w * nxt.x; a2 += kk.w * nxt.y; a3 += kk.w * nxt.z;
            cur = nxt;
        }
    }

    float th = Theta[g];
    float4 ob = *(const float4*)(&g_obs[g][t0 + tid * 4]);
    float4 xo;
    xo.x = a0 + th + ob.x;
    xo.y = a1 + th + ob.y;
    xo.z = a2 + th + ob.z;
    xo.w = a3 + th + ob.w;
    *(float4*)(&g_x[g][t0 + tid * 4]) = xo;
}

// ---------------- threefry2x32 (jax partitionable path) ---------------------
__device__ __forceinline__ uint32_t rotl32(uint32_t x, int r) {
    return (x << r) | (x >> (32 - r));
}
__device__ __forceinline__ void threefry_0_42(uint32_t c0, uint32_t c1,
                                              uint32_t& o0, uint32_t& o1) {
    const uint32_t k0 = 0u, k1 = 42u, k2 = 0x1BD11BDAu ^ 0u ^ 42u;
    uint32_t x0 = c0 + k0, x1 = c1 + k1;
#define RND(r) { x0 += x1; x1 = rotl32(x1, (r)); x1 ^= x0; }
    RND(13) RND(15) RND(26) RND(6)   x0 += k1; x1 += k2 + 1u;
    RND(17) RND(29) RND(16) RND(24)  x0 += k2; x1 += k0 + 2u;
    RND(13) RND(15) RND(26) RND(6)   x0 += k0; x1 += k1 + 3u;
    RND(17) RND(29) RND(16) RND(24)  x0 += k1; x1 += k2 + 4u;
    RND(13) RND(15) RND(26) RND(6)   x0 += k2; x1 += k0 + 5u;
#undef RND
    o0 = x0; o1 = x1;
}

// ---------------- transpose + sigmoid + bernoulli (coalesced [t][g] out) ----
__global__ void __launch_bounds__(256) fin_kernel(float* __restrict__ Zo,
                                                  float* __restrict__ Po_opt) {
    __shared__ float sx[128 * 25];
    float* Po = Po_opt ? Po_opt : g_scratchP;
    int tid = threadIdx.x;
    int t0 = blockIdx.x * 128;

    for (int i = tid; i < 128 * NG; i += 256) {
        int g = i >> 7, tt = i & 127;
        sx[tt * 25 + g] = g_x[g][t0 + tt];
    }
    __syncthreads();

    int base = t0 * NG;
    #pragma unroll
    for (int r = 0; r < 12; ++r) {
        int j = r * 256 + tid;
        int idx = base + j;
        if (idx < NELEM) {
            int tt = j / NG, g = j - tt * NG;
            float x = sx[tt * 25 + g];
            float pf = 1.0f / (1.0f + __expf(-x));
            uint32_t y0, y1;
            threefry_0_42(0u, (uint32_t)idx, y0, y1);
            uint32_t bits = y0 ^ y1;
            float u = __uint_as_float((bits >> 9) | 0x3f800000u) - 1.0f;
            if (fabsf(u - pf) < 1e-4f) {  // tie rescue: exact double path
                double p = 1.0 / (1.0 + exp(-(double)x));
                pf = (float)p;
            }
            Zo[idx] = (u < pf) ? 1.0f : 0.0f;
            Po[idx] = pf;
        }
    }
}

// ---------------- launcher --------------------------------------------------
extern "C" void kernel_launch(void* const* d_in, const int* in_sizes, int n_in,
                              void* d_out, int out_size) {
    const float *Z = 0, *Se = 0, *Si = 0, *Ce = 0, *Ci = 0;
    const float *Wsyn = 0, *Th = 0, *Wobs = 0, *cb = 0, *ob = 0;
    for (int i = 0; i < n_in; ++i) {
        switch (in_sizes[i]) {
            case 100000:    Z    = (const float*)d_in[i]; break;
            case 200000000: Se   = (const float*)d_in[i]; break;
            case 50000000:  Si   = (const float*)d_in[i]; break;
            case 50000:     Ce   = (const float*)d_in[i]; break;
            case 12500:     Ci   = (const float*)d_in[i]; break;
            case 624:       Wsyn = (const float*)d_in[i]; break;
            case 24:        Th   = (const float*)d_in[i]; break;
            case 696:       Wobs = (const float*)d_in[i]; break;
            case 2600:      cb   = (const float*)d_in[i]; break;
            case 11629:     ob   = (const float*)d_in[i]; break;
            default: break;
        }
    }
    float* out = (float*)d_out;
    float* Pdst = (out_size >= 2 * NELEM) ? (out + NELEM) : nullptr;

    const int setup_work = ESYN + ISYN + 2 * NG * TNO + NG * OLEN + NCHUNK;
    setup_kernel<<<(setup_work + 255) / 256, 256>>>(Ce, Ci, Wsyn, Wobs, cb, ob);
    spkb_kernel<<<(T_DATA + 255) / 256, 256>>>(Z);
    obs_kernel<<<NCHUNK, 256>>>();
    bin_kernel<<<T_DATA / 8, 256>>>((const float4*)Se, (const float4*)Si);
    dim3 gridG(NG, (T_DATA + TILE - 1) / TILE);
    glm_kernel<<<gridG, 256>>>(Th);
    fin_kernel<<<(T_DATA + 127) / 128, 256>>>(out, Pdst);
}

// round 5
// speedup vs baseline: 1.5652x; 1.1180x over previous
#include <cuda_runtime.h>
#include <cstdint>
#include <cstddef>

#define T_DATA 100000
#define NG     24
#define TNO    200
#define ESYN   2000
#define ISYN   500
#define NCB    13
#define NOB    29
#define OLEN   401
#define PAD    256
#define SUFF   1536
#define TPAD   (PAD + T_DATA + SUFF)
#define TILE   1024
#define NELEM  (T_DATA * NG)
#define TXP    100352            /* padded T for [g][t] planes */
#define NCHUNK 391               /* ceil(T_DATA/256) spike chunks */

typedef unsigned long long u64;

// ---------------- device scratch (static, zero-initialized) ----------------
__device__ float2   g_syn2[NG][TPAD];   // (E,I) drive pairs, zero pads
__device__ float    g_ke[NG][TNO];      // e kernel (unflipped)
__device__ float    g_ki[NG][TNO];      // i kernel (negated, unflipped)
__device__ float    g_K[NG][OLEN];      // obs kernel K[g][d], d = 200 + t - s
__device__ int      g_idxE[ESYN];
__device__ int      g_idxI[ISYN];
__device__ unsigned g_smask[NCHUNK][8]; // spike bitmask per 256-t chunk
__device__ float    g_obs[NG][TXP];     // obs_filt, [g][t]
__device__ float    g_x[NG][TXP];       // pre-activation
__device__ float    g_scratchP[NELEM];  // fallback P storage

// ---------------- setup ------------------------------------------------------
__global__ void setup_kernel(const float* __restrict__ Ce,
                             const float* __restrict__ Ci,
                             const float* __restrict__ Wsyn,
                             const float* __restrict__ Wobs,
                             const float* __restrict__ cosb,
                             const float* __restrict__ obsb) {
    int k = blockIdx.x * blockDim.x + threadIdx.x;
    if (k < ESYN) {
        int gf = -1;
        for (int r = 1; r <= NG; ++r)
            if (Ce[r * ESYN + k] != 0.0f) gf = r - 1;
        g_idxE[k] = gf;
        return;
    }
    k -= ESYN;
    if (k < ISYN) {
        int gf = -1;
        for (int r = 1; r <= NG; ++r)
            if (Ci[r * ISYN + k] != 0.0f) gf = r - 1;
        g_idxI[k] = gf;
        return;
    }
    k -= ISYN;
    if (k < NG * TNO) {
        int g = k / TNO, j = k % TNO;
        float s = 0.0f;
        for (int b = 0; b < NCB; ++b) {
            float w = Wsyn[(g * NCB + b) * 2 + 0];
            s += (w * w) * cosb[b * TNO + j];
        }
        g_ke[g][j] = s;
        return;
    }
    k -= NG * TNO;
    if (k < NG * TNO) {
        int g = k / TNO, j = k % TNO;
        float s = 0.0f;
        for (int b = 0; b < NCB; ++b) {
            float w = Wsyn[(g * NCB + b) * 2 + 1];
            s += (w * w) * cosb[b * TNO + j];
        }
        g_ki[g][j] = -s;
        return;
    }
    k -= NG * TNO;
    if (k < NG * OLEN) {
        int g = k / OLEN, j = k % OLEN;
        float s = 0.0f;
        for (int b = 0; b < NOB; ++b)
            s += Wobs[g * NOB + b] * obsb[b * OLEN + j];
        g_K[g][j] = s;
        return;
    }
    k -= NG * OLEN;
    if (k < NCHUNK * 8) ((unsigned*)g_smask)[k] = 0u;
}

// ---------------- spike bitmask (order-independent -> deterministic) --------
__global__ void spkb_kernel(const float* __restrict__ Z) {
    int t = blockIdx.x * blockDim.x + threadIdx.x;
    if (t < T_DATA && Z[t] != 0.0f)
        atomicOr(&g_smask[t >> 8][(t >> 5) & 7], 1u << (t & 31));
}

// ---------------- sparse obs (spike-history) filter -------------------------
__global__ void __launch_bounds__(256) obs_kernel() {
    __shared__ float sko[NG][404];
    int tid = threadIdx.x;
    int t0 = blockIdx.x * 256;

    for (int i = tid; i < NG * OLEN; i += 256)
        sko[i / OLEN][i % OLEN] = ((const float*)g_K)[i];
    __syncthreads();

    float acc[NG];
    #pragma unroll
    for (int g = 0; g < NG; ++g) acc[g] = 0.0f;
    int t = t0 + tid;

    int cc = t0 >> 8;
    int c0 = cc > 0 ? cc - 1 : 0;
    int c1 = cc + 1 < NCHUNK ? cc + 1 : NCHUNK - 1;
    for (int c = c0; c <= c1; ++c) {
        #pragma unroll
        for (int w = 0; w < 8; ++w) {
            unsigned bits = g_smask[c][w];
            while (bits) {
                int b = __ffs(bits) - 1;
                bits &= bits - 1;
                int s = (c << 8) + (w << 5) + b;
                int d = t - s + 200;
                if ((unsigned)d <= 400u) {
                    #pragma unroll
                    for (int g = 0; g < NG; ++g) acc[g] += sko[g][d];
                }
            }
        }
    }
    if (t < T_DATA) {
        #pragma unroll
        for (int g = 0; g < NG; ++g) g_obs[g][t] = acc[g];
    }
}

// ---------------- spike binning: MLP-4 streaming kernel ---------------------
__global__ void __launch_bounds__(256) bin_kernel(const float4* __restrict__ Se,
                                                  const float4* __restrict__ Si) {
    __shared__ float sb[8][64];   // [row][0..23]=E bins, [32..55]=I bins
    int w = threadIdx.x >> 5, l = threadIdx.x & 31;
    int t = blockIdx.x * 8 + w;
    for (int i = threadIdx.x; i < 8 * 64; i += 256) ((float*)sb)[i] = 0.0f;
    __syncthreads();

    const float4 z4 = make_float4(0.f, 0.f, 0.f, 0.f);
    const float4* rowE = Se + (size_t)t * (ESYN / 4);
    #pragma unroll
    for (int base = 0; base < 512; base += 128) {
        float4 v[4];
        int idx[4];
        #pragma unroll
        for (int j = 0; j < 4; ++j) {
            int i = base + j * 32 + l;
            idx[j] = i;
            v[j] = (i < ESYN / 4) ? rowE[i] : z4;   // 4 independent loads in flight
        }
        #pragma unroll
        for (int j = 0; j < 4; ++j) {
            float4 vv = v[j];
            int i = idx[j];
            if (vv.x != 0.0f) { int g = g_idxE[4 * i + 0]; if (g >= 0) atomicAdd(&sb[w][g], vv.x); }
            if (vv.y != 0.0f) { int g = g_idxE[4 * i + 1]; if (g >= 0) atomicAdd(&sb[w][g], vv.y); }
            if (vv.z != 0.0f) { int g = g_idxE[4 * i + 2]; if (g >= 0) atomicAdd(&sb[w][g], vv.z); }
            if (vv.w != 0.0f) { int g = g_idxE[4 * i + 3]; if (g >= 0) atomicAdd(&sb[w][g], vv.w); }
        }
    }
    const float4* rowI = Si + (size_t)t * (ISYN / 4);
    {
        float4 v[4];
        int idx[4];
        #pragma unroll
        for (int j = 0; j < 4; ++j) {
            int i = j * 32 + l;
            idx[j] = i;
            v[j] = (i < ISYN / 4) ? rowI[i] : z4;
        }
        #pragma unroll
        for (int j = 0; j < 4; ++j) {
            float4 vv = v[j];
            int i = idx[j];
            if (vv.x != 0.0f) { int g = g_idxI[4 * i + 0]; if (g >= 0) atomicAdd(&sb[w][32 + g], vv.x); }
            if (vv.y != 0.0f) { int g = g_idxI[4 * i + 1]; if (g >= 0) atomicAdd(&sb[w][32 + g], vv.y); }
            if (vv.z != 0.0f) { int g = g_idxI[4 * i + 2]; if (g >= 0) atomicAdd(&sb[w][32 + g], vv.z); }
            if (vv.w != 0.0f) { int g = g_idxI[4 * i + 3]; if (g >= 0) atomicAdd(&sb[w][32 + g], vv.w); }
        }
    }
    __syncthreads();
    for (int kk = threadIdx.x; kk < NG * 8; kk += 256) {
        int g = kk >> 3, row = kk & 7;
        int tt = blockIdx.x * 8 + row;
        g_syn2[g][PAD + tt] = make_float2(sb[row][g], sb[row][32 + g]);
    }
}

// ---------------- packed f32x2 helpers --------------------------------------
__device__ __forceinline__ u64 pk2(float lo, float hi) {
    u64 r;
    asm("mov.b64 %0, {%1, %2};" : "=l"(r) : "f"(lo), "f"(hi));
    return r;
}
__device__ __forceinline__ float2 upk2(u64 v) {
    float2 f;
    asm("mov.b64 {%0, %1}, %2;" : "=f"(f.x), "=f"(f.y) : "l"(v));
    return f;
}
__device__ __forceinline__ void fma2(u64& d, u64 a, u64 b) {
    asm("fma.rn.f32x2 %0, %1, %2, %0;" : "+l"(d) : "l"(a), "l"(b));
}

// ---------------- e/i convs (FFMA2) -> pre-activation x[g][t] ---------------
__global__ void __launch_bounds__(256) glm_kernel(const float* __restrict__ Theta) {
    __shared__ __align__(16) float sE[TILE + 200 + 8];
    __shared__ __align__(16) float sI[TILE + 200 + 8];
    __shared__ __align__(16) float ske[TNO];   // reversed
    __shared__ __align__(16) float ski[TNO];   // reversed

    int g = blockIdx.x;
    int t0 = blockIdx.y * TILE;
    int base = PAD + t0 - 200;

    for (int i = threadIdx.x; i < TILE + 200; i += 256) {
        float2 v = g_syn2[g][base + i];
        sE[i] = v.x; sI[i] = v.y;
    }
    for (int i = threadIdx.x; i < TNO; i += 256) {
        ske[i] = g_ke[g][TNO - 1 - i];
        ski[i] = g_ki[g][TNO - 1 - i];
    }
    __syncthreads();

    const int tid = threadIdx.x;
    u64 a0 = 0ull, a1 = 0ull, a2 = 0ull, a3 = 0ull;  // f32x2 accumulators

    #pragma unroll
    for (int c = 0; c < 2; ++c) {
        const ulonglong2* d2 = (const ulonglong2*)(c == 0 ? sE : sI);
        const ulonglong2* k2 = (const ulonglong2*)(c == 0 ? ske : ski);
        ulonglong2 cur = d2[tid];
        float2 cl = upk2(cur.x), ch = upk2(cur.y);
        #pragma unroll 2
        for (int q = 0; q < TNO / 4; ++q) {
            ulonglong2 kk = k2[q];             // (k0,k1),(k2,k3) reversed taps
            ulonglong2 nx = d2[tid + q + 1];
            float2 nl = upk2(nx.x), nh = upk2(nx.y);
            u64 C = pk2(cl.y, ch.x);           // (c.y,c.z)
            u64 D = pk2(ch.y, nl.x);           // (c.w,n.x)
            u64 F = pk2(nl.y, nh.x);           // (n.y,n.z)
            fma2(a0, kk.x, cur.x); fma2(a0, kk.y, cur.y);
            fma2(a1, kk.x, C);     fma2(a1, kk.y, D);
            fma2(a2, kk.x, cur.y); fma2(a2, kk.y, nx.x);
            fma2(a3, kk.x, D);     fma2(a3, kk.y, F);
            cur = nx; cl = nl; ch = nh;
        }
    }

    float2 r0 = upk2(a0), r1 = upk2(a1), r2 = upk2(a2), r3 = upk2(a3);
    float th = Theta[g];
    float4 ob = *(const float4*)(&g_obs[g][t0 + tid * 4]);
    float4 xo;
    xo.x = (r0.x + r0.y) + th + ob.x;
    xo.y = (r1.x + r1.y) + th + ob.y;
    xo.z = (r2.x + r2.y) + th + ob.z;
    xo.w = (r3.x + r3.y) + th + ob.w;
    *(float4*)(&g_x[g][t0 + tid * 4]) = xo;
}

// ---------------- threefry2x32 (jax partitionable path) ---------------------
__device__ __forceinline__ uint32_t rotl32(uint32_t x, int r) {
    return (x << r) | (x >> (32 - r));
}
__device__ __forceinline__ void threefry_0_42(uint32_t c0, uint32_t c1,
                                              uint32_t& o0, uint32_t& o1) {
    const uint32_t k0 = 0u, k1 = 42u, k2 = 0x1BD11BDAu ^ 0u ^ 42u;
    uint32_t x0 = c0 + k0, x1 = c1 + k1;
#define RND(r) { x0 += x1; x1 = rotl32(x1, (r)); x1 ^= x0; }
    RND(13) RND(15) RND(26) RND(6)   x0 += k1; x1 += k2 + 1u;
    RND(17) RND(29) RND(16) RND(24)  x0 += k2; x1 += k0 + 2u;
    RND(13) RND(15) RND(26) RND(6)   x0 += k0; x1 += k1 + 3u;
    RND(17) RND(29) RND(16) RND(24)  x0 += k1; x1 += k2 + 4u;
    RND(13) RND(15) RND(26) RND(6)   x0 += k2; x1 += k0 + 5u;
#undef RND
    o0 = x0; o1 = x1;
}

// ---------------- transpose + sigmoid + bernoulli ---------------------------
__global__ void __launch_bounds__(256) fin_kernel(float* __restrict__ Zo,
                                                  float* __restrict__ Po_opt) {
    __shared__ float sx[128 * 25];
    float* Po = Po_opt ? Po_opt : g_scratchP;
    int tid = threadIdx.x;
    int t0 = blockIdx.x * 128;

    for (int i = tid; i < 128 * NG; i += 256) {
        int g = i >> 7, tt = i & 127;
        sx[tt * 25 + g] = g_x[g][t0 + tt];
    }
    __syncthreads();

    int base = t0 * NG;
    #pragma unroll
    for (int r = 0; r < 12; ++r) {
        int j = r * 256 + tid;
        int idx = base + j;
        if (idx < NELEM) {
            int tt = j / NG, g = j - tt * NG;
            float x = sx[tt * 25 + g];
            float pf = 1.0f / (1.0f + __expf(-x));
            uint32_t y0, y1;
            threefry_0_42(0u, (uint32_t)idx, y0, y1);
            uint32_t bits = y0 ^ y1;
            float u = __uint_as_float((bits >> 9) | 0x3f800000u) - 1.0f;
            if (fabsf(u - pf) < 1e-4f) {  // tie rescue: exact double path
                double p = 1.0 / (1.0 + exp(-(double)x));
                pf = (float)p;
            }
            Zo[idx] = (u < pf) ? 1.0f : 0.0f;
            Po[idx] = pf;
        }
    }
}

// ---------------- launcher --------------------------------------------------
extern "C" void kernel_launch(void* const* d_in, const int* in_sizes, int n_in,
                              void* d_out, int out_size) {
    const float *Z = 0, *Se = 0, *Si = 0, *Ce = 0, *Ci = 0;
    const float *Wsyn = 0, *Th = 0, *Wobs = 0, *cb = 0, *ob = 0;
    for (int i = 0; i < n_in; ++i) {
        switch (in_sizes[i]) {
            case 100000:    Z    = (const float*)d_in[i]; break;
            case 200000000: Se   = (const float*)d_in[i]; break;
            case 50000000:  Si   = (const float*)d_in[i]; break;
            case 50000:     Ce   = (const float*)d_in[i]; break;
            case 12500:     Ci   = (const float*)d_in[i]; break;
            case 624:       Wsyn = (const float*)d_in[i]; break;
            case 24:        Th   = (const float*)d_in[i]; break;
            case 696:       Wobs = (const float*)d_in[i]; break;
            case 2600:      cb   = (const float*)d_in[i]; break;
            case 11629:     ob   = (const float*)d_in[i]; break;
            default: break;
        }
    }
    float* out = (float*)d_out;
    float* Pdst = (out_size >= 2 * NELEM) ? (out + NELEM) : nullptr;

    const int setup_work = ESYN + ISYN + 2 * NG * TNO + NG * OLEN + NCHUNK * 8;
    setup_kernel<<<(setup_work + 255) / 256, 256>>>(Ce, Ci, Wsyn, Wobs, cb, ob);
    spkb_kernel<<<(T_DATA + 255) / 256, 256>>>(Z);
    obs_kernel<<<NCHUNK, 256>>>();
    bin_kernel<<<T_DATA / 8, 256>>>((const float4*)Se, (const float4*)Si);
    dim3 gridG(NG, (T_DATA + TILE - 1) / TILE);
    glm_kernel<<<gridG, 256>>>(Th);
    fin_kernel<<<(T_DATA + 127) / 128, 256>>>(out, Pdst);
}